// round 14
// baseline (speedup 1.0000x reference)
#include <cuda_runtime.h>
#include <cuda_bf16.h>
#include <stdint.h>
#include <math.h>

#define Dc 1024

// ------------------------- scratch (__device__ globals) ---------------------
__device__ __align__(128) __nv_bfloat16 g_hid_hi[8192*1024];
__device__ __align__(128) __nv_bfloat16 g_hid_lo[8192*1024];
__device__ __align__(128) __nv_bfloat16 g_src_hi[8192*1024];
__device__ __align__(128) __nv_bfloat16 g_src_lo[8192*1024];
__device__ __align__(128) __nv_bfloat16 g_wt_hi[5*1024*1024];
__device__ __align__(128) __nv_bfloat16 g_wt_lo[5*1024*1024];
__device__ __align__(128) __nv_bfloat16 g_qq2_hi[(size_t)128*1024*128];
__device__ __align__(128) __nv_bfloat16 g_qq2_lo[(size_t)128*1024*128];
__device__ __align__(128) __nv_bfloat16 g_kk2_hi[(size_t)128*1024*128];
__device__ __align__(128) __nv_bfloat16 g_kk2_lo[(size_t)128*1024*128];
__device__ __align__(128) __nv_bfloat16 g_vt_hi[(size_t)128*64*1024];
__device__ __align__(128) __nv_bfloat16 g_vt_lo[(size_t)128*64*1024];

// ------------------------- warp-MMA / async helpers --------------------------
__device__ __forceinline__ uint32_t smem_u32(const void* p) {
    uint32_t a;
    asm("{ .reg .u64 t; cvta.to.shared.u64 t, %1; cvt.u32.u64 %0, t; }" : "=r"(a) : "l"(p));
    return a;
}
__device__ __forceinline__ void ldsm4(uint32_t* r, uint32_t addr) {
    asm volatile("ldmatrix.sync.aligned.m8n8.x4.shared.b16 {%0,%1,%2,%3}, [%4];"
        : "=r"(r[0]), "=r"(r[1]), "=r"(r[2]), "=r"(r[3]) : "r"(addr));
}
__device__ __forceinline__ void mma16816(float* c, const uint32_t* a, uint32_t b0, uint32_t b1) {
    asm volatile(
        "mma.sync.aligned.m16n8k16.row.col.f32.bf16.bf16.f32 "
        "{%0,%1,%2,%3}, {%4,%5,%6,%7}, {%8,%9}, {%0,%1,%2,%3};"
        : "+f"(c[0]), "+f"(c[1]), "+f"(c[2]), "+f"(c[3])
        : "r"(a[0]), "r"(a[1]), "r"(a[2]), "r"(a[3]), "r"(b0), "r"(b1));
}
__device__ __forceinline__ void cpa16(uint32_t dst, const void* src) {
    asm volatile("cp.async.cg.shared.global [%0], [%1], 16;" :: "r"(dst), "l"(src) : "memory");
}
#define CP_COMMIT() asm volatile("cp.async.commit_group;" ::: "memory")
#define CP_WAIT0()  asm volatile("cp.async.wait_group 0;" ::: "memory")
#define CP_WAIT1()  asm volatile("cp.async.wait_group 1;" ::: "memory")

__device__ __forceinline__ void store_hilo2(__nv_bfloat16* hi, __nv_bfloat16* lo, size_t o,
                                            float x0, float x1) {
    __nv_bfloat16 h0 = __float2bfloat16(x0), h1 = __float2bfloat16(x1);
    __nv_bfloat162 hp; hp.x = h0; hp.y = h1;
    __nv_bfloat162 lp;
    lp.x = __float2bfloat16(x0 - __bfloat162float(h0));
    lp.y = __float2bfloat16(x1 - __bfloat162float(h1));
    *(__nv_bfloat162*)&hi[o] = hp;
    *(__nv_bfloat162*)&lo[o] = lp;
}

// smem tile layout: rows of 40 bf16 (32 data + 8 pad) = 80B stride
#define TSTR 40
#define SA_HI 0
#define SA_LO 10240
#define SB_HI 20480
#define SB_LO 30720
#define STAGE_BIG   40960

// proj 128x256 stage: A hi/lo (10KB each) + B256 hi/lo (20KB each) = 60KB
#define PA_HI 0
#define PA_LO 10240
#define PB_HI 20480
#define PB_LO 40960
#define STAGE_PROJ 61440

// async-load a 128-row BK=32 tile into a stage buffer
__device__ __forceinline__ void cp_tile128(uint32_t smbase, const __nv_bfloat16* src,
                                           int ld, int k0, int tid) {
    #pragma unroll
    for (int i = 0; i < 2; i++) {
        int idx = tid + i * 256;
        int r = idx >> 2, c8 = (idx & 3) << 3;
        cpa16(smbase + (uint32_t)(r * TSTR + c8) * 2, src + (size_t)r * ld + k0 + c8);
    }
}
// async-load a 256-row BK=32 tile
__device__ __forceinline__ void cp_tile256(uint32_t smbase, const __nv_bfloat16* src,
                                           int ld, int k0, int tid) {
    #pragma unroll
    for (int i = 0; i < 4; i++) {
        int idx = tid + i * 256;
        int r = idx >> 2, c8 = (idx & 3) << 3;
        cpa16(smbase + (uint32_t)(r * TSTR + c8) * 2, src + (size_t)r * ld + k0 + c8);
    }
}

// merged 3-pass chunk for 32x64 warp tiles (attn phase A) — 24 LDSM/chunk.
__device__ __forceinline__ void mma_chunk_attnA(uint32_t sb, int wm, int wn, int lane,
                                                float acc[2][8][4]) {
    int arow = (lane & 7) + ((lane >> 3) & 1) * 8;
    int acol = (lane >> 4) * 8;
    #pragma unroll
    for (int ks = 0; ks < 2; ks++) {
        uint32_t ah[2][4], al[2][4];
        #pragma unroll
        for (int mi = 0; mi < 2; mi++) {
            ldsm4(ah[mi], sb + SA_HI + (uint32_t)((wm*32 + mi*16 + arow)*TSTR + ks*16 + acol)*2);
            ldsm4(al[mi], sb + SA_LO + (uint32_t)((wm*32 + mi*16 + arow)*TSTR + ks*16 + acol)*2);
        }
        #pragma unroll
        for (int nb = 0; nb < 4; nb++) {
            uint32_t bt[4];
            ldsm4(bt, sb + SB_HI + (uint32_t)((wn*64 + nb*16 + arow)*TSTR + ks*16 + acol)*2);
            #pragma unroll
            for (int mi = 0; mi < 2; mi++) {
                mma16816(acc[mi][nb*2],     ah[mi], bt[0], bt[2]);
                mma16816(acc[mi][nb*2 + 1], ah[mi], bt[1], bt[3]);
                mma16816(acc[mi][nb*2],     al[mi], bt[0], bt[2]);
                mma16816(acc[mi][nb*2 + 1], al[mi], bt[1], bt[3]);
            }
        }
        #pragma unroll
        for (int nb = 0; nb < 4; nb++) {
            uint32_t bt[4];
            ldsm4(bt, sb + SB_LO + (uint32_t)((wn*64 + nb*16 + arow)*TSTR + ks*16 + acol)*2);
            #pragma unroll
            for (int mi = 0; mi < 2; mi++) {
                mma16816(acc[mi][nb*2],     ah[mi], bt[0], bt[2]);
                mma16816(acc[mi][nb*2 + 1], ah[mi], bt[1], bt[3]);
            }
        }
    }
}

// merged 3-pass chunk for 64x64 warp tiles (proj 128x256) — 32 LDSM/chunk.
__device__ __forceinline__ void mma_chunk_64x64(uint32_t sb, int wm, int wn, int lane,
                                                float acc[4][8][4]) {
    int arow = (lane & 7) + ((lane >> 3) & 1) * 8;
    int acol = (lane >> 4) * 8;
    #pragma unroll
    for (int ks = 0; ks < 2; ks++) {
        uint32_t ah[4][4], al[4][4];
        #pragma unroll
        for (int mi = 0; mi < 4; mi++) {
            ldsm4(ah[mi], sb + PA_HI + (uint32_t)((wm*64 + mi*16 + arow)*TSTR + ks*16 + acol)*2);
            ldsm4(al[mi], sb + PA_LO + (uint32_t)((wm*64 + mi*16 + arow)*TSTR + ks*16 + acol)*2);
        }
        #pragma unroll
        for (int nb = 0; nb < 4; nb++) {
            uint32_t bt[4];
            ldsm4(bt, sb + PB_HI + (uint32_t)((wn*64 + nb*16 + arow)*TSTR + ks*16 + acol)*2);
            #pragma unroll
            for (int mi = 0; mi < 4; mi++) {
                mma16816(acc[mi][nb*2],     ah[mi], bt[0], bt[2]);
                mma16816(acc[mi][nb*2 + 1], ah[mi], bt[1], bt[3]);
                mma16816(acc[mi][nb*2],     al[mi], bt[0], bt[2]);
                mma16816(acc[mi][nb*2 + 1], al[mi], bt[1], bt[3]);
            }
        }
        #pragma unroll
        for (int nb = 0; nb < 4; nb++) {
            uint32_t bt[4];
            ldsm4(bt, sb + PB_LO + (uint32_t)((wn*64 + nb*16 + arow)*TSTR + ks*16 + acol)*2);
            #pragma unroll
            for (int mi = 0; mi < 4; mi++) {
                mma16816(acc[mi][nb*2],     ah[mi], bt[0], bt[2]);
                mma16816(acc[mi][nb*2 + 1], ah[mi], bt[1], bt[3]);
            }
        }
    }
}

// attn phase B: P(hi/lo) x V(hi/lo), merged — 20 LDSM/chunk.
__device__ __forceinline__ void mma_pv_chunk(uint32_t pbase, uint32_t vbase, int wid, int lane,
                                             float acc[8][4]) {
    int arow = (lane & 7) + ((lane >> 3) & 1) * 8;
    int acol = (lane >> 4) * 8;
    #pragma unroll
    for (int ks = 0; ks < 2; ks++) {
        uint32_t ah[4], al[4];
        ldsm4(ah, pbase +         (uint32_t)((wid*16 + arow)*TSTR + ks*16 + acol)*2);
        ldsm4(al, pbase + 10240 + (uint32_t)((wid*16 + arow)*TSTR + ks*16 + acol)*2);
        #pragma unroll
        for (int nb = 0; nb < 4; nb++) {
            uint32_t bt[4];
            ldsm4(bt, vbase + (uint32_t)((nb*16 + arow)*TSTR + ks*16 + acol)*2);
            mma16816(acc[nb*2],     ah, bt[0], bt[2]);
            mma16816(acc[nb*2 + 1], ah, bt[1], bt[3]);
            mma16816(acc[nb*2],     al, bt[0], bt[2]);
            mma16816(acc[nb*2 + 1], al, bt[1], bt[3]);
        }
        #pragma unroll
        for (int nb = 0; nb < 4; nb++) {
            uint32_t bt[4];
            ldsm4(bt, vbase + 5120 + (uint32_t)((nb*16 + arow)*TSTR + ks*16 + acol)*2);
            mma16816(acc[nb*2],     ah, bt[0], bt[2]);
            mma16816(acc[nb*2 + 1], ah, bt[1], bt[3]);
        }
    }
}

// ------------------------- conversion kernels --------------------------------
__global__ __launch_bounds__(256) void split_acts(const float* __restrict__ hid,
                                                  const float* __restrict__ src)
{
    int which = blockIdx.x >= 8192;
    const float* in = which ? src : hid;
    __nv_bfloat16* hi = which ? g_src_hi : g_hid_hi;
    __nv_bfloat16* lo = which ? g_src_lo : g_hid_lo;
    size_t i = ((size_t)(blockIdx.x & 8191) * 256 + threadIdx.x) * 4;
    float4 v = *(const float4*)(in + i);
    float x[4] = {v.x, v.y, v.z, v.w};
    #pragma unroll
    for (int j = 0; j < 4; j++) {
        __nv_bfloat16 h = __float2bfloat16(x[j]);
        hi[i + j] = h;
        lo[i + j] = __float2bfloat16(x[j] - __bfloat162float(h));
    }
}

__global__ __launch_bounds__(256) void split_wt(
    const float* __restrict__ Wq, const float* __restrict__ Wk, const float* __restrict__ Wv,
    const float* __restrict__ Wq2, const float* __restrict__ Wk2)
{
    __shared__ float t[32][33];
    int w = blockIdx.z;
    const float* W = (w==0)?Wq:(w==1)?Wk:(w==2)?Wv:(w==3)?Wq2:Wk2;
    int tx = threadIdx.x & 31, ty = threadIdx.x >> 5;
    int n0 = blockIdx.x * 32, k0 = blockIdx.y * 32;
    #pragma unroll
    for (int j = 0; j < 32; j += 8)
        t[ty + j][tx] = W[(size_t)(k0 + ty + j) * Dc + n0 + tx];
    __syncthreads();
    size_t woff = (size_t)w * Dc * Dc;
    #pragma unroll
    for (int j = 0; j < 32; j += 8) {
        float x = t[tx][ty + j];
        __nv_bfloat16 h = __float2bfloat16(x);
        size_t o = woff + (size_t)(n0 + ty + j) * Dc + k0 + tx;
        g_wt_hi[o] = h;
        g_wt_lo[o] = __float2bfloat16(x - __bfloat162float(h));
    }
}

// ------------------------- projection GEMM (128x256 tile) --------------------
// grid (4, 64, 5), block 256, occ 1. 8 warps of 64x64. 2-stage cp.async.
__global__ __launch_bounds__(256, 1) void proj_gemm(
    const float* __restrict__ bq, const float* __restrict__ bk, const float* __restrict__ bv,
    const float* __restrict__ bq2, const float* __restrict__ bk2)
{
    extern __shared__ __align__(16) char sm[];
    uint32_t smb = smem_u32(sm);
    int w = blockIdx.z, nT = blockIdx.x, mT = blockIdx.y;
    const __nv_bfloat16* Ah = ((w == 4) ? g_src_hi : g_hid_hi) + (size_t)mT * 128 * Dc;
    const __nv_bfloat16* Al = ((w == 4) ? g_src_lo : g_hid_lo) + (size_t)mT * 128 * Dc;
    size_t woff = (size_t)w * Dc * Dc + (size_t)nT * 256 * Dc;
    const __nv_bfloat16* Bh = g_wt_hi + woff;
    const __nv_bfloat16* Bl = g_wt_lo + woff;
    const float* bias = (w==0)?bq:(w==1)?bk:(w==2)?bv:(w==3)?bq2:bk2;

    int tid = threadIdx.x, lane = tid & 31, wid = tid >> 5;
    int wm = wid & 1, wn = wid >> 1;      // 2 M-blocks x 4 N-blocks of 64

    float acc[4][8][4];
    #pragma unroll
    for (int a = 0; a < 4; a++)
        #pragma unroll
        for (int b = 0; b < 8; b++)
            #pragma unroll
            for (int c = 0; c < 4; c++) acc[a][b][c] = 0.f;

    cp_tile128(smb + PA_HI, Ah, Dc, 0, tid);
    cp_tile128(smb + PA_LO, Al, Dc, 0, tid);
    cp_tile256(smb + PB_HI, Bh, Dc, 0, tid);
    cp_tile256(smb + PB_LO, Bl, Dc, 0, tid);
    CP_COMMIT();

    for (int c = 0; c < 32; c++) {
        CP_WAIT0();
        __syncthreads();
        if (c + 1 < 32) {
            uint32_t sb = smb + ((c + 1) & 1) * STAGE_PROJ;
            int kn = (c + 1) * 32;
            cp_tile128(sb + PA_HI, Ah, Dc, kn, tid);
            cp_tile128(sb + PA_LO, Al, Dc, kn, tid);
            cp_tile256(sb + PB_HI, Bh, Dc, kn, tid);
            cp_tile256(sb + PB_LO, Bl, Dc, kn, tid);
            CP_COMMIT();
        }
        mma_chunk_64x64(smb + (c & 1) * STAGE_PROJ, wm, wn, lane, acc);
    }
    __syncthreads();

    // Epilogue: stage per 64-col group through smem, add bias, scatter.
    float* sf = (float*)sm;
    int mBase = mT * 128, b = mBase >> 10, l0 = mBase & 1023;
    for (int grp = 0; grp < 4; grp++) {
        if (wn == grp) {
            #pragma unroll
            for (int mi = 0; mi < 4; mi++)
                #pragma unroll
                for (int ni = 0; ni < 8; ni++) {
                    int r0 = wm*64 + mi*16 + (lane >> 2);
                    int c0 = ni*8 + (lane & 3)*2;
                    sf[r0*72 + c0]     = acc[mi][ni][0];
                    sf[r0*72 + c0 + 1] = acc[mi][ni][1];
                    sf[(r0+8)*72 + c0]     = acc[mi][ni][2];
                    sf[(r0+8)*72 + c0 + 1] = acc[mi][ni][3];
                }
        }
        __syncthreads();
        int head = nT*4 + grp;
        int bh = b*16 + head;
        if (w == 2) {   // V: transpose -> vt[bh][hd][l]
            for (int idx = tid; idx < 64*128; idx += 256) {
                int hd = idx >> 7, ll = idx & 127;
                float x = sf[ll*72 + hd] + __ldg(&bias[head*64 + hd]);
                __nv_bfloat16 h = __float2bfloat16(x);
                size_t o = ((size_t)bh*64 + hd)*1024 + l0 + ll;
                g_vt_hi[o] = h;
                g_vt_lo[o] = __float2bfloat16(x - __bfloat162float(h));
            }
        } else {
            __nv_bfloat16* dhi = (w == 0 || w == 3) ? g_qq2_hi : g_kk2_hi;
            __nv_bfloat16* dlo = (w == 0 || w == 3) ? g_qq2_lo : g_kk2_lo;
            int co = (w >= 3) ? 64 : 0;
            for (int idx = tid; idx < 128*32; idx += 256) {
                int r = idx >> 5, c2 = (idx & 31)*2;
                float x0 = sf[r*72 + c2]     + __ldg(&bias[head*64 + c2]);
                float x1 = sf[r*72 + c2 + 1] + __ldg(&bias[head*64 + c2 + 1]);
                store_hilo2(dhi, dlo, ((size_t)bh*1024 + l0 + r)*128 + co + c2, x0, x1);
            }
        }
        __syncthreads();
    }
}

// ------------------------- fused attention (unchanged from R13) --------------
#define AST(i)   ((uint32_t)(i) * 40960u)
#define FV_BASE  122880
#define FRS_BASE 163840
#define FUSED_SMEM 164864
__global__ __launch_bounds__(256, 1) void attn_fused(const float* __restrict__ mask,
                                                     float* __restrict__ out)
{
    extern __shared__ __align__(16) char sm[];
    uint32_t smb = smem_u32(sm);
    int mT = blockIdx.x, bh = blockIdx.y;
    int tid = threadIdx.x, lane = tid & 31, wid = tid >> 5;
    int wm = wid & 3, wn = wid >> 2;
    int b = bh >> 4, h = bh & 15;

    const __nv_bfloat16* Qh = g_qq2_hi + ((size_t)bh*1024 + mT*128) * 128;
    const __nv_bfloat16* Ql = g_qq2_lo + ((size_t)bh*1024 + mT*128) * 128;
    const __nv_bfloat16* KhB = g_kk2_hi + (size_t)bh*1024*128;
    const __nv_bfloat16* KlB = g_kk2_lo + (size_t)bh*1024*128;
    const __nv_bfloat16* Vh = g_vt_hi + (size_t)bh*64*1024;
    const __nv_bfloat16* Vl = g_vt_lo + (size_t)bh*64*1024;

    float acc_o[8][4];
    #pragma unroll
    for (int i = 0; i < 8; i++)
        #pragma unroll
        for (int j = 0; j < 4; j++) acc_o[i][j] = 0.f;
    float rs[2][2] = {{0.f, 0.f}, {0.f, 0.f}};

    {
        cp_tile128(smb + AST(2) + SA_HI, Qh, 128, 0, tid);
        cp_tile128(smb + AST(2) + SA_LO, Ql, 128, 0, tid);
        cp_tile128(smb + AST(2) + SB_HI, KhB, 128, 0, tid);
        cp_tile128(smb + AST(2) + SB_LO, KlB, 128, 0, tid);
        CP_COMMIT();
        cp_tile128(smb + AST(0) + SA_HI, Qh, 128, 32, tid);
        cp_tile128(smb + AST(0) + SA_LO, Ql, 128, 32, tid);
        cp_tile128(smb + AST(0) + SB_HI, KhB, 128, 32, tid);
        cp_tile128(smb + AST(0) + SB_LO, KlB, 128, 32, tid);
        CP_COMMIT();
    }

    for (int nT = 0; nT < 8; nT++) {
        const __nv_bfloat16* Kh = KhB + (size_t)nT*128*128;
        const __nv_bfloat16* Kl = KlB + (size_t)nT*128*128;

        float acc_s[2][8][4];
        #pragma unroll
        for (int a = 0; a < 2; a++)
            #pragma unroll
            for (int bb = 0; bb < 8; bb++)
                #pragma unroll
                for (int c = 0; c < 4; c++) acc_s[a][bb][c] = 0.f;

        #pragma unroll
        for (int c = 0; c < 4; c++) {
            if (c < 3) { CP_WAIT1(); } else { CP_WAIT0(); }
            __syncthreads();
            if (c <= 1) {
                uint32_t sb = smb + AST((c + 1) % 3);
                int kn = (c + 2) * 32;
                cp_tile128(sb + SA_HI, Qh, 128, kn, tid);
                cp_tile128(sb + SA_LO, Ql, 128, kn, tid);
                cp_tile128(sb + SB_HI, Kh, 128, kn, tid);
                cp_tile128(sb + SB_LO, Kl, 128, kn, tid);
                CP_COMMIT();
            }
            mma_chunk_attnA(smb + AST((c + 2) % 3), wm, wn, lane, acc_s);
        }
        __syncthreads();

        {
            int r = tid >> 2, c8 = (tid & 3) << 3;
            #pragma unroll
            for (int c2 = 0; c2 < 4; c2++) {
                cpa16(smb + FV_BASE + c2*10240 +        (uint32_t)(r*TSTR + c8)*2,
                      Vh + (size_t)r*1024 + nT*128 + c2*32 + c8);
                cpa16(smb + FV_BASE + c2*10240 + 5120 + (uint32_t)(r*TSTR + c8)*2,
                      Vl + (size_t)r*1024 + nT*128 + c2*32 + c8);
            }
            if (nT < 7) {
                const __nv_bfloat16* Kh2 = KhB + (size_t)(nT+1)*128*128;
                const __nv_bfloat16* Kl2 = KlB + (size_t)(nT+1)*128*128;
                cp_tile128(smb + AST(2) + SA_HI, Qh, 128, 0, tid);
                cp_tile128(smb + AST(2) + SA_LO, Ql, 128, 0, tid);
                cp_tile128(smb + AST(2) + SB_HI, Kh2, 128, 0, tid);
                cp_tile128(smb + AST(2) + SB_LO, Kl2, 128, 0, tid);
            }
            CP_COMMIT();
        }

        #pragma unroll
        for (int ni = 0; ni < 8; ni++) {
            int c = wn*64 + ni*8 + (lane & 3)*2;
            float mk0 = __ldg(&mask[(size_t)b*1024 + nT*128 + c]);
            float mk1 = __ldg(&mask[(size_t)b*1024 + nT*128 + c + 1]);
            int c2 = c >> 5, cc = c & 31;
            __nv_bfloat16* phi = (__nv_bfloat16*)(sm + c2*20480);
            __nv_bfloat16* plo = (__nv_bfloat16*)(sm + c2*20480 + 10240);
            #pragma unroll
            for (int mi = 0; mi < 2; mi++) {
                int r0 = wm*32 + mi*16 + (lane >> 2);
                float p0 = __expf(acc_s[mi][ni][0]*0.125f + mk0);
                float p1 = __expf(acc_s[mi][ni][1]*0.125f + mk1);
                float p2 = __expf(acc_s[mi][ni][2]*0.125f + mk0);
                float p3 = __expf(acc_s[mi][ni][3]*0.125f + mk1);
                rs[mi][0] += p0 + p1;
                rs[mi][1] += p2 + p3;
                store_hilo2(phi, plo, (size_t)(r0*TSTR + cc), p0, p1);
                store_hilo2(phi, plo, (size_t)((r0 + 8)*TSTR + cc), p2, p3);
            }
        }
        CP_WAIT0();
        __syncthreads();

        #pragma unroll
        for (int c2 = 0; c2 < 4; c2++)
            mma_pv_chunk(smb + c2*20480, smb + FV_BASE + c2*10240, wid, lane, acc_o);
        __syncthreads();

        if (nT < 7) {
            const __nv_bfloat16* Kh2 = KhB + (size_t)(nT+1)*128*128;
            const __nv_bfloat16* Kl2 = KlB + (size_t)(nT+1)*128*128;
            cp_tile128(smb + AST(0) + SA_HI, Qh, 128, 32, tid);
            cp_tile128(smb + AST(0) + SA_LO, Ql, 128, 32, tid);
            cp_tile128(smb + AST(0) + SB_HI, Kh2, 128, 32, tid);
            cp_tile128(smb + AST(0) + SB_LO, Kl2, 128, 32, tid);
            CP_COMMIT();
        }
    }

    float* rssm = (float*)(sm + FRS_BASE);
    #pragma unroll
    for (int mi = 0; mi < 2; mi++)
        #pragma unroll
        for (int hf = 0; hf < 2; hf++) {
            float v = rs[mi][hf];
            v += __shfl_xor_sync(0xffffffffu, v, 1);
            v += __shfl_xor_sync(0xffffffffu, v, 2);
            if ((lane & 3) == 0) {
                int r = wm*32 + mi*16 + (lane >> 2) + hf*8;
                rssm[r*2 + wn] = v;
            }
        }
    __syncthreads();

    int rloc0 = wid*16 + (lane >> 2);
    float l0 = rssm[rloc0*2] + rssm[rloc0*2 + 1];
    float l1 = rssm[(rloc0 + 8)*2] + rssm[(rloc0 + 8)*2 + 1];
    float inv0 = 1.f / l0, inv1 = 1.f / l1;
    int r0 = mT*128 + rloc0;
    #pragma unroll
    for (int ni = 0; ni < 8; ni++) {
        int c = h*64 + ni*8 + (lane & 3)*2;
        *(float2*)&out[((size_t)b*1024 + r0)*1024 + c] =
            make_float2(acc_o[ni][0]*inv0, acc_o[ni][1]*inv0);
        *(float2*)&out[((size_t)b*1024 + r0 + 8)*1024 + c] =
            make_float2(acc_o[ni][2]*inv1, acc_o[ni][3]*inv1);
    }
}

// ------------------------- launch --------------------------------------------
extern "C" void kernel_launch(void* const* d_in, const int* in_sizes, int n_in,
                              void* d_out, int out_size)
{
    (void)in_sizes; (void)n_in; (void)out_size;
    const float* hidden = (const float*)d_in[0];
    const float* mask   = (const float*)d_in[1];
    const float* source = (const float*)d_in[2];
    const float* bq  = (const float*)d_in[4];
    const float* bk  = (const float*)d_in[6];
    const float* bv  = (const float*)d_in[8];
    const float* bq2 = (const float*)d_in[10];
    const float* bk2 = (const float*)d_in[12];
    float* out = (float*)d_out;

    static int attr_done = 0;
    if (!attr_done) {
        cudaFuncSetAttribute(proj_gemm,  cudaFuncAttributeMaxDynamicSharedMemorySize, 2*STAGE_PROJ);
        cudaFuncSetAttribute(attn_fused, cudaFuncAttributeMaxDynamicSharedMemorySize, FUSED_SMEM);
        attr_done = 1;
    }

    split_acts<<<16384, 256>>>(hidden, source);
    split_wt<<<dim3(32, 32, 5), 256>>>((const float*)d_in[3], (const float*)d_in[5],
                                       (const float*)d_in[7], (const float*)d_in[9],
                                       (const float*)d_in[11]);
    proj_gemm<<<dim3(4, 64, 5), 256, 2*STAGE_PROJ>>>(bq, bk, bv, bq2, bk2);
    attn_fused<<<dim3(8, 128), 256, FUSED_SMEM>>>(mask, out);
}